// round 12
// baseline (speedup 1.0000x reference)
#include <cuda_runtime.h>
#include <cuda_bf16.h>
#include <math.h>
#include <stdint.h>

// Problem constants
#define BB 2
#define TT 2048
#define CC 1024
#define HH 16
#define HD 64
#define M_TOT (BB*TT)        // 4096
#define N_QKV (3*CC)         // 3072

// Scratch (device globals: allocation-free)
__device__ __nv_bfloat16 g_xh[M_TOT*CC],  g_xl[M_TOT*CC];
__device__ __nv_bfloat16 g_wah[N_QKV*CC], g_wal[N_QKV*CC];
__device__ __nv_bfloat16 g_wph[CC*CC],    g_wpl[CC*CC];
__device__ __nv_bfloat16 g_qh[BB*HH*TT*HD], g_ql[BB*HH*TT*HD];
__device__ __nv_bfloat16 g_kh[BB*HH*TT*HD], g_kl[BB*HH*TT*HD];
__device__ __nv_bfloat16 g_vh[BB*HH*TT*HD], g_vl[BB*HH*TT*HD];
__device__ __nv_bfloat16 g_yh[BB*TT*CC], g_yl[BB*TT*CC];

#define SW128(off)    ((off) ^ (((off) >> 3) & 0x70))

__device__ __forceinline__ uint32_t smem_u32(const void* p) {
    uint32_t a;
    asm("{ .reg .u64 t; cvta.to.shared.u64 t, %1; cvt.u32.u64 %0, t; }" : "=r"(a) : "l"(p));
    return a;
}

#define LDSM_X4(r0, r1, r2, r3, addr) \
    asm volatile("ldmatrix.sync.aligned.m8n8.x4.shared.b16 {%0,%1,%2,%3}, [%4];" \
                 : "=r"(r0), "=r"(r1), "=r"(r2), "=r"(r3) : "r"(addr))

#define LDSM_X4_T(r0, r1, r2, r3, addr) \
    asm volatile("ldmatrix.sync.aligned.m8n8.x4.trans.shared.b16 {%0,%1,%2,%3}, [%4];" \
                 : "=r"(r0), "=r"(r1), "=r"(r2), "=r"(r3) : "r"(addr))

#define MMA_BF16(d, a0, a1, a2, a3, b0, b1) \
    asm volatile("mma.sync.aligned.m16n8k16.row.col.f32.bf16.bf16.f32 " \
                 "{%0,%1,%2,%3}, {%4,%5,%6,%7}, {%8,%9}, {%0,%1,%2,%3};" \
                 : "+f"((d)[0]), "+f"((d)[1]), "+f"((d)[2]), "+f"((d)[3]) \
                 : "r"(a0), "r"(a1), "r"(a2), "r"(a3), "r"(b0), "r"(b1))

__device__ __forceinline__ void cp16(uint32_t dst, const void* src) {
    asm volatile("cp.async.cg.shared.global [%0], [%1], 16;" :: "r"(dst), "l"(src));
}
#define CP_COMMIT()   asm volatile("cp.async.commit_group;" ::: "memory")
#define CP_WAIT(n)    asm volatile("cp.async.wait_group %0;" :: "n"(n) : "memory")

__device__ __forceinline__ float hi_trunc(float x) {
    return __uint_as_float(__float_as_uint(x) & 0xFFFF0000u);
}
__device__ __forceinline__ uint32_t pack2_hi(float x, float y) {
    return (__float_as_uint(x) >> 16) | (__float_as_uint(y) & 0xFFFF0000u);
}
__device__ __forceinline__ uint32_t pack2_rn(float x, float y) {
    uint32_t r;
    asm("cvt.rn.bf16x2.f32 %0, %1, %2;" : "=r"(r) : "f"(y), "f"(x));
    return r;
}

// ===========================================================================
// One-time fp32 -> bf16 hi/lo split
// ===========================================================================
__global__ __launch_bounds__(256) void convert_split(
    const float4* __restrict__ src, uint32_t* __restrict__ hi,
    uint32_t* __restrict__ lo, int n4)
{
    int i = blockIdx.x * blockDim.x + threadIdx.x;
    if (i >= n4) return;
    float4 v = src[i];
    uint2 h, l;
    h.x = pack2_hi(v.x, v.y);
    h.y = pack2_hi(v.z, v.w);
    l.x = pack2_rn(v.x - hi_trunc(v.x), v.y - hi_trunc(v.y));
    l.y = pack2_rn(v.z - hi_trunc(v.z), v.w - hi_trunc(v.w));
    reinterpret_cast<uint2*>(hi)[i] = h;
    reinterpret_cast<uint2*>(lo)[i] = l;
}

// ===========================================================================
// Pipelined tensor-core GEMM on pre-split bf16 (unchanged from R10)
// ===========================================================================
#define SM_BUF   65536
#define SM_TOTAL (2*SM_BUF)

template<int MODE>
__global__ __launch_bounds__(256) void gemm_tc(
    const float* __restrict__ bias, float* __restrict__ C, int K, int N)
{
    extern __shared__ char smem[];
    uint32_t sb  = smem_u32(smem);
    int tid = threadIdx.x;
    int wid = tid >> 5;
    int lid = tid & 31;

    const __nv_bfloat16 *Ah, *Al, *Bh, *Bl;
    if (MODE == 1) { Ah = g_xh; Al = g_xl; Bh = g_wah; Bl = g_wal; }
    else           { Ah = g_yh; Al = g_yl; Bh = g_wph; Bl = g_wpl; }

    int m0 = blockIdx.y * 128;
    int n0 = blockIdx.x * 128;

    int mw = (wid >> 2) * 64;
    int nw = (wid & 3)  * 32;

    int a_row = lid & 15;
    int a_cb  = (lid >> 4) * 16;
    int b_row = (lid & 7) + ((lid >> 4) << 3);
    int b_cb  = ((lid >> 3) & 1) * 16;

    int s_row[4], s_ch[4];
#pragma unroll
    for (int i = 0; i < 4; i++) {
        int idx = tid + i * 256;
        s_row[i] = idx >> 3;
        s_ch[i]  = idx & 7;
    }

    const int nchunk = K / 64;

    auto stage = [&](int kc, int buf) {
        uint32_t base = sb + buf * SM_BUF;
        const __nv_bfloat16* srcs[4] = {
            Ah + (size_t)m0 * K + kc * 64, Al + (size_t)m0 * K + kc * 64,
            Bh + (size_t)n0 * K + kc * 64, Bl + (size_t)n0 * K + kc * 64 };
#pragma unroll
        for (int t = 0; t < 4; t++)
#pragma unroll
            for (int i = 0; i < 4; i++)
                cp16(base + t * 16384 + SW128((uint32_t)(s_row[i]*128 + s_ch[i]*16)),
                     srcs[t] + (size_t)s_row[i] * K + s_ch[i] * 8);
        CP_COMMIT();
    };

    float acc[16][4];
#pragma unroll
    for (int i = 0; i < 16; i++)
#pragma unroll
        for (int j = 0; j < 4; j++) acc[i][j] = 0.f;

    stage(0, 0);

    for (int kc = 0; kc < nchunk; kc++) {
        int cur = kc & 1;
        if (kc + 1 < nchunk) { stage(kc + 1, cur ^ 1); CP_WAIT(1); }
        else                 { CP_WAIT(0); }
        __syncthreads();

        uint32_t bufb = sb + cur * SM_BUF;
#pragma unroll
        for (int p = 0; p < 3; p++) {
            uint32_t abase = bufb + (p == 2 ? 16384 : 0);
            uint32_t bbase = bufb + (p == 1 ? 49152 : 32768);
#pragma unroll
            for (int ks = 0; ks < 4; ks++) {
                uint32_t af[4][4];
#pragma unroll
                for (int mi = 0; mi < 4; mi++) {
                    uint32_t addr = abase +
                        SW128((uint32_t)((mw + mi*16 + a_row) * 128 + ks*32 + a_cb));
                    LDSM_X4(af[mi][0], af[mi][1], af[mi][2], af[mi][3], addr);
                }
                uint32_t bf[2][4];
#pragma unroll
                for (int nn = 0; nn < 2; nn++) {
                    uint32_t addr = bbase +
                        SW128((uint32_t)((nw + nn*16 + b_row) * 128 + ks*32 + b_cb));
                    LDSM_X4(bf[nn][0], bf[nn][1], bf[nn][2], bf[nn][3], addr);
                }
#pragma unroll
                for (int mi = 0; mi < 4; mi++)
#pragma unroll
                    for (int ni = 0; ni < 4; ni++) {
                        uint32_t bb0 = bf[ni >> 1][(ni & 1) * 2];
                        uint32_t bb1 = bf[ni >> 1][(ni & 1) * 2 + 1];
                        MMA_BF16(acc[mi*4+ni],
                                 af[mi][0], af[mi][1], af[mi][2], af[mi][3], bb0, bb1);
                    }
            }
        }
        __syncthreads();
    }

    int g  = lid >> 2;
    int t4 = lid & 3;
#pragma unroll
    for (int mi = 0; mi < 4; mi++) {
        int mrow0 = m0 + mw + mi*16 + g;
        int mrow1 = mrow0 + 8;
#pragma unroll
        for (int ni = 0; ni < 4; ni++) {
            int n = n0 + nw + ni*8 + 2*t4;
            float bv0 = bias[n], bv1 = bias[n+1];
            const float* a4 = acc[mi*4+ni];
            float2 v0; v0.x = a4[0] + bv0; v0.y = a4[1] + bv1;
            float2 v1; v1.x = a4[2] + bv0; v1.y = a4[3] + bv1;

            if (MODE == 1) {
                int which = n >> 10;
                int h = (n >> 6) & 15;
                int d = n & 63;
                __nv_bfloat16* ph_ = (which == 0 ? g_qh : which == 1 ? g_kh : g_vh);
                __nv_bfloat16* pl_ = (which == 0 ? g_ql : which == 1 ? g_kl : g_vl);
                {
                    int bb = mrow0 >> 11, t = mrow0 & 2047;
                    size_t i0 = ((((size_t)bb*HH + h)*TT) + t)*HD + d;
                    ((uint32_t*)ph_)[i0 >> 1] = pack2_hi(v0.x, v0.y);
                    ((uint32_t*)pl_)[i0 >> 1] =
                        pack2_rn(v0.x - hi_trunc(v0.x), v0.y - hi_trunc(v0.y));
                }
                {
                    int bb = mrow1 >> 11, t = mrow1 & 2047;
                    size_t i1 = ((((size_t)bb*HH + h)*TT) + t)*HD + d;
                    ((uint32_t*)ph_)[i1 >> 1] = pack2_hi(v1.x, v1.y);
                    ((uint32_t*)pl_)[i1 >> 1] =
                        pack2_rn(v1.x - hi_trunc(v1.x), v1.y - hi_trunc(v1.y));
                }
            } else {
                *reinterpret_cast<float2*>(C + (size_t)mrow0 * N + n) = v0;
                *reinterpret_cast<float2*>(C + (size_t)mrow1 * N + n) = v1;
            }
        }
    }
}

// ===========================================================================
// Tensor-core flash attention v2: 128-row Q blocks, 8 warps, cp.async
// double-buffered K/V staging, heaviest-first block order.
// Block x covers q rows [128x, 128x+128), iterates kt = 0 .. 2x+1.
// ===========================================================================
#define ASM_Q     0         // qh 16KB @0, ql 16KB @16384
#define ASM_BUF0  32768     // each buf: Kh@0, Kl@8192, Vh@16384, Vl@24576
#define ASM_TOTAL 98304     // 96 KB

__global__ __launch_bounds__(256) void attn_tc()
{
    extern __shared__ char asmem[];
    uint32_t sb = smem_u32(asmem);

    int tid = threadIdx.x;
    int wid = tid >> 5;
    int lid = tid & 31;
    int x   = (int)gridDim.x - 1 - (int)blockIdx.x;   // heaviest first
    int bh  = blockIdx.y;
    int q0  = x * 128;
    size_t hoff = (size_t)bh * (TT * HD);

    int g  = lid >> 2;
    int t4 = lid & 3;

    // ---- stage Q tile (synchronous, once) ----
    {
        const uint4* qh4 = reinterpret_cast<const uint4*>(g_qh + hoff + (size_t)q0*HD);
        const uint4* ql4 = reinterpret_cast<const uint4*>(g_ql + hoff + (size_t)q0*HD);
#pragma unroll
        for (int i = 0; i < 4; i++) {
            int idx = tid + i*256;               // 1024 chunks: 128 rows x 8
            int row = idx >> 3, ch = idx & 7;
            uint32_t sw = SW128((uint32_t)(row*128 + ch*16));
            *reinterpret_cast<uint4*>(asmem + ASM_Q + sw)         = qh4[row*8 + ch];
            *reinterpret_cast<uint4*>(asmem + ASM_Q + 16384 + sw) = ql4[row*8 + ch];
        }
    }
    __syncthreads();

    uint32_t qh[4][4], ql[4][4];
    int a_row = lid & 15, a_cb = (lid >> 4) * 16;
#pragma unroll
    for (int ks = 0; ks < 4; ks++) {
        uint32_t off = SW128((uint32_t)((wid*16 + a_row)*128 + ks*32 + a_cb));
        LDSM_X4(qh[ks][0], qh[ks][1], qh[ks][2], qh[ks][3], sb + ASM_Q + off);
        LDSM_X4(ql[ks][0], ql[ks][1], ql[ks][2], ql[ks][3], sb + ASM_Q + 16384 + off);
    }
    __syncthreads();   // Q smem free (not reused, but fragments are loaded)

    float o[8][4];
#pragma unroll
    for (int i = 0; i < 8; i++)
#pragma unroll
        for (int j = 0; j < 4; j++) o[i][j] = 0.f;
    float m0 = -INFINITY, m1 = -INFINITY, l0 = 0.f, l1 = 0.f;

    int b_row = (lid & 7) + ((lid >> 4) << 3);
    int b_cb  = ((lid >> 3) & 1) * 16;
    int v_row = (lid & 7) + (((lid >> 3) & 1) << 3);
    int v_cb  = (lid >> 4) << 4;

    // cp.async K/V staging: 2048 16B chunks (4 arrays x 512), 8 per thread
    auto stageKV = [&](int kt, uint32_t base) {
        size_t toff = hoff + (size_t)kt*64*HD;
        const __nv_bfloat16* arrs[4] = { g_kh + toff, g_kl + toff,
                                         g_vh + toff, g_vl + toff };
#pragma unroll
        for (int i = 0; i < 8; i++) {
            int idx = tid + i*256;
            int t   = idx >> 9;
            int c   = idx & 511;
            int row = c >> 3, ch = c & 7;
            cp16(base + t*8192 + SW128((uint32_t)(row*128 + ch*16)),
                 arrs[t] + (size_t)row*HD + ch*8);
        }
        CP_COMMIT();
    };

    const int ntiles = 2*x + 2;
    stageKV(0, sb + ASM_BUF0);

    for (int kt = 0; kt < ntiles; kt++) {
        uint32_t bufb = sb + ASM_BUF0 + (uint32_t)(kt & 1) * 32768;
        if (kt + 1 < ntiles) { stageKV(kt + 1, sb + ASM_BUF0 + (uint32_t)((kt+1)&1)*32768); CP_WAIT(1); }
        else                 { CP_WAIT(0); }
        __syncthreads();

        int dk = kt - 2*x;   // >=0: diagonal region
        // second diagonal tile: warps with all rows < 64+? fully masked -> skip
        bool skip = (dk == 1) && (wid < 4);

        if (!skip) {
            uint32_t skh = bufb, skl = bufb + 8192;
            uint32_t svh = bufb + 16384, svl = bufb + 24576;

            // ---- S = Q K^T (3 passes) ----
            float s[8][4];
#pragma unroll
            for (int i = 0; i < 8; i++)
#pragma unroll
                for (int j = 0; j < 4; j++) s[i][j] = 0.f;

#pragma unroll
            for (int ks = 0; ks < 4; ks++) {
#pragma unroll
                for (int nn = 0; nn < 4; nn++) {
                    uint32_t off = SW128((uint32_t)((nn*16 + b_row)*128 + ks*32 + b_cb));
                    uint32_t k0, k1, k2, k3, c0, c1, c2, c3;
                    LDSM_X4(k0, k1, k2, k3, skh + off);
                    LDSM_X4(c0, c1, c2, c3, skl + off);
                    MMA_BF16(s[nn*2],   qh[ks][0], qh[ks][1], qh[ks][2], qh[ks][3], k0, k1);
                    MMA_BF16(s[nn*2+1], qh[ks][0], qh[ks][1], qh[ks][2], qh[ks][3], k2, k3);
                    MMA_BF16(s[nn*2],   qh[ks][0], qh[ks][1], qh[ks][2], qh[ks][3], c0, c1);
                    MMA_BF16(s[nn*2+1], qh[ks][0], qh[ks][1], qh[ks][2], qh[ks][3], c2, c3);
                    MMA_BF16(s[nn*2],   ql[ks][0], ql[ks][1], ql[ks][2], ql[ks][3], k0, k1);
                    MMA_BF16(s[nn*2+1], ql[ks][0], ql[ks][1], ql[ks][2], ql[ks][3], k2, k3);
                }
            }

            // ---- scale + causal mask ----
            if (dk >= 0) {
#pragma unroll
                for (int ni = 0; ni < 8; ni++)
#pragma unroll
                    for (int j = 0; j < 4; j++) {
                        int ct  = ni*8 + 2*t4 + (j & 1);
                        int rt  = wid*16 + g + ((j >> 1) << 3);
                        int lim = rt - dk*64;
                        s[ni][j] = (ct <= lim) ? s[ni][j] * 0.125f : -INFINITY;
                    }
            } else {
#pragma unroll
                for (int ni = 0; ni < 8; ni++)
#pragma unroll
                    for (int j = 0; j < 4; j++) s[ni][j] *= 0.125f;
            }

            // ---- online softmax ----
            float mt0 = m0, mt1 = m1;
#pragma unroll
            for (int ni = 0; ni < 8; ni++) {
                mt0 = fmaxf(mt0, fmaxf(s[ni][0], s[ni][1]));
                mt1 = fmaxf(mt1, fmaxf(s[ni][2], s[ni][3]));
            }
            mt0 = fmaxf(mt0, __shfl_xor_sync(0xffffffffu, mt0, 1));
            mt0 = fmaxf(mt0, __shfl_xor_sync(0xffffffffu, mt0, 2));
            mt1 = fmaxf(mt1, __shfl_xor_sync(0xffffffffu, mt1, 1));
            mt1 = fmaxf(mt1, __shfl_xor_sync(0xffffffffu, mt1, 2));

            float alpha0 = __expf(m0 - mt0);
            float alpha1 = __expf(m1 - mt1);
            m0 = mt0; m1 = mt1;

            float ps0 = 0.f, ps1 = 0.f;
#pragma unroll
            for (int ni = 0; ni < 8; ni++) {
                s[ni][0] = __expf(s[ni][0] - m0);
                s[ni][1] = __expf(s[ni][1] - m0);
                s[ni][2] = __expf(s[ni][2] - m1);
                s[ni][3] = __expf(s[ni][3] - m1);
                ps0 += s[ni][0] + s[ni][1];
                ps1 += s[ni][2] + s[ni][3];
            }
            ps0 += __shfl_xor_sync(0xffffffffu, ps0, 1);
            ps0 += __shfl_xor_sync(0xffffffffu, ps0, 2);
            ps1 += __shfl_xor_sync(0xffffffffu, ps1, 1);
            ps1 += __shfl_xor_sync(0xffffffffu, ps1, 2);
            l0 = l0 * alpha0 + ps0;
            l1 = l1 * alpha1 + ps1;

#pragma unroll
            for (int dt = 0; dt < 8; dt++) {
                o[dt][0] *= alpha0; o[dt][1] *= alpha0;
                o[dt][2] *= alpha1; o[dt][3] *= alpha1;
            }

            // ---- P fragments, split hi/lo in regs ----
            uint32_t ph[4][4], pl[4][4];
#pragma unroll
            for (int kc = 0; kc < 4; kc++) {
                float x0 = s[2*kc][0],   x1 = s[2*kc][1],   x2 = s[2*kc][2],   x3 = s[2*kc][3];
                float y0 = s[2*kc+1][0], y1 = s[2*kc+1][1], y2 = s[2*kc+1][2], y3 = s[2*kc+1][3];
                ph[kc][0] = pack2_hi(x0, x1);
                ph[kc][1] = pack2_hi(x2, x3);
                ph[kc][2] = pack2_hi(y0, y1);
                ph[kc][3] = pack2_hi(y2, y3);
                pl[kc][0] = pack2_rn(x0 - hi_trunc(x0), x1 - hi_trunc(x1));
                pl[kc][1] = pack2_rn(x2 - hi_trunc(x2), x3 - hi_trunc(x3));
                pl[kc][2] = pack2_rn(y0 - hi_trunc(y0), y1 - hi_trunc(y1));
                pl[kc][3] = pack2_rn(y2 - hi_trunc(y2), y3 - hi_trunc(y3));
            }

            // ---- O += P V (3 passes, V via ldmatrix.trans) ----
#pragma unroll
            for (int kc = 0; kc < 4; kc++) {
#pragma unroll
                for (int dn = 0; dn < 4; dn++) {
                    uint32_t off = SW128((uint32_t)((kc*16 + v_row)*128 + dn*32 + v_cb));
                    uint32_t vh0, vh1, vh2, vh3, vl0, vl1, vl2, vl3;
                    LDSM_X4_T(vh0, vh1, vh2, vh3, svh + off);
                    LDSM_X4_T(vl0, vl1, vl2, vl3, svl + off);
                    MMA_BF16(o[dn*2],   ph[kc][0], ph[kc][1], ph[kc][2], ph[kc][3], vh0, vh1);
                    MMA_BF16(o[dn*2+1], ph[kc][0], ph[kc][1], ph[kc][2], ph[kc][3], vh2, vh3);
                    MMA_BF16(o[dn*2],   ph[kc][0], ph[kc][1], ph[kc][2], ph[kc][3], vl0, vl1);
                    MMA_BF16(o[dn*2+1], ph[kc][0], ph[kc][1], ph[kc][2], ph[kc][3], vl2, vl3);
                    MMA_BF16(o[dn*2],   pl[kc][0], pl[kc][1], pl[kc][2], pl[kc][3], vh0, vh1);
                    MMA_BF16(o[dn*2+1], pl[kc][0], pl[kc][1], pl[kc][2], pl[kc][3], vh2, vh3);
                }
            }
        }
        __syncthreads();   // all warps done with this buffer before re-stage
    }

    // ---- epilogue: normalize, write split bf16 into g_yh/g_yl ----
    float inv0 = 1.f / l0, inv1 = 1.f / l1;
    int b = bh >> 4, h = bh & 15;
    int row0 = q0 + wid*16 + g;
    int row1 = row0 + 8;
    size_t off0 = ((size_t)b*TT + row0)*CC + h*HD;
    size_t off1 = ((size_t)b*TT + row1)*CC + h*HD;
#pragma unroll
    for (int dt = 0; dt < 8; dt++) {
        int d = dt*8 + 2*t4;
        float w0x = o[dt][0]*inv0, w0y = o[dt][1]*inv0;
        float w1x = o[dt][2]*inv1, w1y = o[dt][3]*inv1;
        ((uint32_t*)g_yh)[(off0 + d) >> 1] = pack2_hi(w0x, w0y);
        ((uint32_t*)g_yl)[(off0 + d) >> 1] =
            pack2_rn(w0x - hi_trunc(w0x), w0y - hi_trunc(w0y));
        ((uint32_t*)g_yh)[(off1 + d) >> 1] = pack2_hi(w1x, w1y);
        ((uint32_t*)g_yl)[(off1 + d) >> 1] =
            pack2_rn(w1x - hi_trunc(w1x), w1y - hi_trunc(w1y));
    }
}

// ---------------------------------------------------------------------------
extern "C" void kernel_launch(void* const* d_in, const int* in_sizes, int n_in,
                              void* d_out, int out_size)
{
    const float* x      = (const float*)d_in[0];
    const float* W_attn = (const float*)d_in[1];
    const float* b_attn = (const float*)d_in[2];
    const float* W_proj = (const float*)d_in[3];
    const float* b_proj = (const float*)d_in[4];
    float* out = (float*)d_out;

    cudaFuncSetAttribute(gemm_tc<1>, cudaFuncAttributeMaxDynamicSharedMemorySize, SM_TOTAL);
    cudaFuncSetAttribute(gemm_tc<2>, cudaFuncAttributeMaxDynamicSharedMemorySize, SM_TOTAL);
    cudaFuncSetAttribute(attn_tc,    cudaFuncAttributeMaxDynamicSharedMemorySize, ASM_TOTAL);

    // 0) one-time splits
    {
        __nv_bfloat16 *xh, *xl, *wah, *wal, *wph, *wpl;
        cudaGetSymbolAddress((void**)&xh,  g_xh);
        cudaGetSymbolAddress((void**)&xl,  g_xl);
        cudaGetSymbolAddress((void**)&wah, g_wah);
        cudaGetSymbolAddress((void**)&wal, g_wal);
        cudaGetSymbolAddress((void**)&wph, g_wph);
        cudaGetSymbolAddress((void**)&wpl, g_wpl);
        int n4x = M_TOT*CC/4, n4a = N_QKV*CC/4, n4p = CC*CC/4;
        convert_split<<<(n4x+255)/256, 256>>>((const float4*)x,
            (uint32_t*)xh, (uint32_t*)xl, n4x);
        convert_split<<<(n4a+255)/256, 256>>>((const float4*)W_attn,
            (uint32_t*)wah, (uint32_t*)wal, n4a);
        convert_split<<<(n4p+255)/256, 256>>>((const float4*)W_proj,
            (uint32_t*)wph, (uint32_t*)wpl, n4p);
    }

    // 1) QKV projection
    gemm_tc<1><<<dim3(N_QKV/128, M_TOT/128), 256, SM_TOTAL>>>(b_attn, nullptr, CC, N_QKV);
    // 2) causal flash attention (128-row Q blocks, cp.async pipelined)
    attn_tc<<<dim3(TT/128, BB*HH), 256, ASM_TOTAL>>>();
    // 3) output projection
    gemm_tc<2><<<dim3(CC/128, M_TOT/128), 256, SM_TOTAL>>>(b_proj, out, CC, CC);
}

// round 13
// speedup vs baseline: 1.6303x; 1.6303x over previous
#include <cuda_runtime.h>
#include <cuda_bf16.h>
#include <math.h>
#include <stdint.h>

// Problem constants
#define BB 2
#define TT 2048
#define CC 1024
#define HH 16
#define HD 64
#define M_TOT (BB*TT)        // 4096
#define N_QKV (3*CC)         // 3072

// Scratch (device globals: allocation-free)
__device__ __nv_bfloat16 g_xh[M_TOT*CC],  g_xl[M_TOT*CC];
__device__ __nv_bfloat16 g_wah[N_QKV*CC], g_wal[N_QKV*CC];
__device__ __nv_bfloat16 g_wph[CC*CC],    g_wpl[CC*CC];
__device__ __nv_bfloat16 g_qh[BB*HH*TT*HD], g_ql[BB*HH*TT*HD];
__device__ __nv_bfloat16 g_kh[BB*HH*TT*HD], g_kl[BB*HH*TT*HD];
__device__ __nv_bfloat16 g_vh[BB*HH*TT*HD], g_vl[BB*HH*TT*HD];
__device__ __nv_bfloat16 g_yh[BB*TT*CC], g_yl[BB*TT*CC];

#define SW128(off)    ((off) ^ (((off) >> 3) & 0x70))

__device__ __forceinline__ uint32_t smem_u32(const void* p) {
    uint32_t a;
    asm("{ .reg .u64 t; cvta.to.shared.u64 t, %1; cvt.u32.u64 %0, t; }" : "=r"(a) : "l"(p));
    return a;
}

#define LDSM_X4(r0, r1, r2, r3, addr) \
    asm volatile("ldmatrix.sync.aligned.m8n8.x4.shared.b16 {%0,%1,%2,%3}, [%4];" \
                 : "=r"(r0), "=r"(r1), "=r"(r2), "=r"(r3) : "r"(addr))

#define LDSM_X4_T(r0, r1, r2, r3, addr) \
    asm volatile("ldmatrix.sync.aligned.m8n8.x4.trans.shared.b16 {%0,%1,%2,%3}, [%4];" \
                 : "=r"(r0), "=r"(r1), "=r"(r2), "=r"(r3) : "r"(addr))

#define MMA_BF16(d, a0, a1, a2, a3, b0, b1) \
    asm volatile("mma.sync.aligned.m16n8k16.row.col.f32.bf16.bf16.f32 " \
                 "{%0,%1,%2,%3}, {%4,%5,%6,%7}, {%8,%9}, {%0,%1,%2,%3};" \
                 : "+f"((d)[0]), "+f"((d)[1]), "+f"((d)[2]), "+f"((d)[3]) \
                 : "r"(a0), "r"(a1), "r"(a2), "r"(a3), "r"(b0), "r"(b1))

__device__ __forceinline__ void cp16(uint32_t dst, const void* src) {
    asm volatile("cp.async.cg.shared.global [%0], [%1], 16;" :: "r"(dst), "l"(src));
}
#define CP_COMMIT()   asm volatile("cp.async.commit_group;" ::: "memory")
#define CP_WAIT(n)    asm volatile("cp.async.wait_group %0;" :: "n"(n) : "memory")

__device__ __forceinline__ float hi_trunc(float x) {
    return __uint_as_float(__float_as_uint(x) & 0xFFFF0000u);
}
__device__ __forceinline__ uint32_t pack2_hi(float x, float y) {
    return (__float_as_uint(x) >> 16) | (__float_as_uint(y) & 0xFFFF0000u);
}
__device__ __forceinline__ uint32_t pack2_rn(float x, float y) {
    uint32_t r;
    asm("cvt.rn.bf16x2.f32 %0, %1, %2;" : "=r"(r) : "f"(y), "f"(x));
    return r;
}

// ===========================================================================
// One-time fp32 -> bf16 hi/lo split
// ===========================================================================
__global__ __launch_bounds__(256) void convert_split(
    const float4* __restrict__ src, uint32_t* __restrict__ hi,
    uint32_t* __restrict__ lo, int n4)
{
    int i = blockIdx.x * blockDim.x + threadIdx.x;
    if (i >= n4) return;
    float4 v = src[i];
    uint2 h, l;
    h.x = pack2_hi(v.x, v.y);
    h.y = pack2_hi(v.z, v.w);
    l.x = pack2_rn(v.x - hi_trunc(v.x), v.y - hi_trunc(v.y));
    l.y = pack2_rn(v.z - hi_trunc(v.z), v.w - hi_trunc(v.w));
    reinterpret_cast<uint2*>(hi)[i] = h;
    reinterpret_cast<uint2*>(lo)[i] = l;
}

// ===========================================================================
// Pipelined tensor-core GEMM on pre-split bf16 (byte-identical to R10)
// ===========================================================================
#define SM_BUF   65536
#define SM_TOTAL (2*SM_BUF)

template<int MODE>
__global__ __launch_bounds__(256) void gemm_tc(
    const float* __restrict__ bias, float* __restrict__ C, int K, int N)
{
    extern __shared__ char smem[];
    uint32_t sb  = smem_u32(smem);
    int tid = threadIdx.x;
    int wid = tid >> 5;
    int lid = tid & 31;

    const __nv_bfloat16 *Ah, *Al, *Bh, *Bl;
    if (MODE == 1) { Ah = g_xh; Al = g_xl; Bh = g_wah; Bl = g_wal; }
    else           { Ah = g_yh; Al = g_yl; Bh = g_wph; Bl = g_wpl; }

    int m0 = blockIdx.y * 128;
    int n0 = blockIdx.x * 128;

    int mw = (wid >> 2) * 64;
    int nw = (wid & 3)  * 32;

    int a_row = lid & 15;
    int a_cb  = (lid >> 4) * 16;
    int b_row = (lid & 7) + ((lid >> 4) << 3);
    int b_cb  = ((lid >> 3) & 1) * 16;

    int s_row[4], s_ch[4];
#pragma unroll
    for (int i = 0; i < 4; i++) {
        int idx = tid + i * 256;
        s_row[i] = idx >> 3;
        s_ch[i]  = idx & 7;
    }

    const int nchunk = K / 64;

    auto stage = [&](int kc, int buf) {
        uint32_t base = sb + buf * SM_BUF;
        const __nv_bfloat16* srcs[4] = {
            Ah + (size_t)m0 * K + kc * 64, Al + (size_t)m0 * K + kc * 64,
            Bh + (size_t)n0 * K + kc * 64, Bl + (size_t)n0 * K + kc * 64 };
#pragma unroll
        for (int t = 0; t < 4; t++)
#pragma unroll
            for (int i = 0; i < 4; i++)
                cp16(base + t * 16384 + SW128((uint32_t)(s_row[i]*128 + s_ch[i]*16)),
                     srcs[t] + (size_t)s_row[i] * K + s_ch[i] * 8);
        CP_COMMIT();
    };

    float acc[16][4];
#pragma unroll
    for (int i = 0; i < 16; i++)
#pragma unroll
        for (int j = 0; j < 4; j++) acc[i][j] = 0.f;

    stage(0, 0);

    for (int kc = 0; kc < nchunk; kc++) {
        int cur = kc & 1;
        if (kc + 1 < nchunk) { stage(kc + 1, cur ^ 1); CP_WAIT(1); }
        else                 { CP_WAIT(0); }
        __syncthreads();

        uint32_t bufb = sb + cur * SM_BUF;
#pragma unroll
        for (int p = 0; p < 3; p++) {
            uint32_t abase = bufb + (p == 2 ? 16384 : 0);
            uint32_t bbase = bufb + (p == 1 ? 49152 : 32768);
#pragma unroll
            for (int ks = 0; ks < 4; ks++) {
                uint32_t af[4][4];
#pragma unroll
                for (int mi = 0; mi < 4; mi++) {
                    uint32_t addr = abase +
                        SW128((uint32_t)((mw + mi*16 + a_row) * 128 + ks*32 + a_cb));
                    LDSM_X4(af[mi][0], af[mi][1], af[mi][2], af[mi][3], addr);
                }
                uint32_t bf[2][4];
#pragma unroll
                for (int nn = 0; nn < 2; nn++) {
                    uint32_t addr = bbase +
                        SW128((uint32_t)((nw + nn*16 + b_row) * 128 + ks*32 + b_cb));
                    LDSM_X4(bf[nn][0], bf[nn][1], bf[nn][2], bf[nn][3], addr);
                }
#pragma unroll
                for (int mi = 0; mi < 4; mi++)
#pragma unroll
                    for (int ni = 0; ni < 4; ni++) {
                        uint32_t bb0 = bf[ni >> 1][(ni & 1) * 2];
                        uint32_t bb1 = bf[ni >> 1][(ni & 1) * 2 + 1];
                        MMA_BF16(acc[mi*4+ni],
                                 af[mi][0], af[mi][1], af[mi][2], af[mi][3], bb0, bb1);
                    }
            }
        }
        __syncthreads();
    }

    int g  = lid >> 2;
    int t4 = lid & 3;
#pragma unroll
    for (int mi = 0; mi < 4; mi++) {
        int mrow0 = m0 + mw + mi*16 + g;
        int mrow1 = mrow0 + 8;
#pragma unroll
        for (int ni = 0; ni < 4; ni++) {
            int n = n0 + nw + ni*8 + 2*t4;
            float bv0 = bias[n], bv1 = bias[n+1];
            const float* a4 = acc[mi*4+ni];
            float2 v0; v0.x = a4[0] + bv0; v0.y = a4[1] + bv1;
            float2 v1; v1.x = a4[2] + bv0; v1.y = a4[3] + bv1;

            if (MODE == 1) {
                int which = n >> 10;
                int h = (n >> 6) & 15;
                int d = n & 63;
                __nv_bfloat16* ph_ = (which == 0 ? g_qh : which == 1 ? g_kh : g_vh);
                __nv_bfloat16* pl_ = (which == 0 ? g_ql : which == 1 ? g_kl : g_vl);
                {
                    int bb = mrow0 >> 11, t = mrow0 & 2047;
                    size_t i0 = ((((size_t)bb*HH + h)*TT) + t)*HD + d;
                    ((uint32_t*)ph_)[i0 >> 1] = pack2_hi(v0.x, v0.y);
                    ((uint32_t*)pl_)[i0 >> 1] =
                        pack2_rn(v0.x - hi_trunc(v0.x), v0.y - hi_trunc(v0.y));
                }
                {
                    int bb = mrow1 >> 11, t = mrow1 & 2047;
                    size_t i1 = ((((size_t)bb*HH + h)*TT) + t)*HD + d;
                    ((uint32_t*)ph_)[i1 >> 1] = pack2_hi(v1.x, v1.y);
                    ((uint32_t*)pl_)[i1 >> 1] =
                        pack2_rn(v1.x - hi_trunc(v1.x), v1.y - hi_trunc(v1.y));
                }
            } else {
                *reinterpret_cast<float2*>(C + (size_t)mrow0 * N + n) = v0;
                *reinterpret_cast<float2*>(C + (size_t)mrow1 * N + n) = v1;
            }
        }
    }
}

// ===========================================================================
// Tensor-core flash attention (R10 shape: 64-row Q tile, 4 warps, 128 thr)
// + cp.async double-buffered K/V staging (2 x 32 KB dynamic smem)
// + heaviest-first block order.
// ===========================================================================
#define AB_SIZE   32768      // per buffer: Kh@0, Kl@8192, Vh@16384, Vl@24576
#define ASM_TOTAL (2*AB_SIZE)

__global__ __launch_bounds__(128) void attn_tc()
{
    extern __shared__ char asmem[];
    uint32_t sb = smem_u32(asmem);

    int tid = threadIdx.x;
    int wid = tid >> 5;
    int lid = tid & 31;
    int qt  = (int)gridDim.x - 1 - (int)blockIdx.x;   // heaviest first
    int bh  = blockIdx.y;
    int q0  = qt * 64;
    size_t hoff = (size_t)bh * (TT * HD);

    int g  = lid >> 2;
    int t4 = lid & 3;

    // ---- stage Q tile into buf0 (Kh/Kl slots), build Q fragments ----
    {
        const uint4* srch = reinterpret_cast<const uint4*>(g_qh + hoff + (size_t)q0*HD);
        const uint4* srcl = reinterpret_cast<const uint4*>(g_ql + hoff + (size_t)q0*HD);
#pragma unroll
        for (int i = 0; i < 4; i++) {
            int idx = tid + i*128;               // 512 chunks: 64 rows x 8
            int row = idx >> 3, ch = idx & 7;
            uint32_t sw = SW128((uint32_t)(row*128 + ch*16));
            *reinterpret_cast<uint4*>(asmem + sw)        = srch[row*8 + ch];
            *reinterpret_cast<uint4*>(asmem + 8192 + sw) = srcl[row*8 + ch];
        }
    }
    __syncthreads();

    uint32_t qh[4][4], ql[4][4];
    int a_row = lid & 15, a_cb = (lid >> 4) * 16;
#pragma unroll
    for (int ks = 0; ks < 4; ks++) {
        uint32_t off = SW128((uint32_t)((wid*16 + a_row)*128 + ks*32 + a_cb));
        LDSM_X4(qh[ks][0], qh[ks][1], qh[ks][2], qh[ks][3], sb + off);
        LDSM_X4(ql[ks][0], ql[ks][1], ql[ks][2], ql[ks][3], sb + 8192 + off);
    }
    __syncthreads();   // Q read complete before buf0 is re-staged with K/V

    float o[8][4];
#pragma unroll
    for (int i = 0; i < 8; i++)
#pragma unroll
        for (int j = 0; j < 4; j++) o[i][j] = 0.f;
    float m0 = -INFINITY, m1 = -INFINITY, l0 = 0.f, l1 = 0.f;

    int b_row = (lid & 7) + ((lid >> 4) << 3);
    int b_cb  = ((lid >> 3) & 1) * 16;
    int v_row = (lid & 7) + (((lid >> 3) & 1) << 3);
    int v_cb  = (lid >> 4) << 4;

    // cp.async K/V staging: 2048 16B chunks (4 arrays x 512), 16 per thread
    auto stageKV = [&](int kt, uint32_t base) {
        size_t toff = hoff + (size_t)kt*64*HD;
        const __nv_bfloat16* arrs[4] = { g_kh + toff, g_kl + toff,
                                         g_vh + toff, g_vl + toff };
#pragma unroll
        for (int i = 0; i < 16; i++) {
            int idx = tid + i*128;
            int t   = idx >> 9;
            int c   = idx & 511;
            int row = c >> 3, ch = c & 7;
            cp16(base + t*8192 + SW128((uint32_t)(row*128 + ch*16)),
                 arrs[t] + (size_t)row*HD + ch*8);
        }
        CP_COMMIT();
    };

    const int ntiles = qt + 1;
    stageKV(0, sb);

    for (int kt = 0; kt < ntiles; kt++) {
        uint32_t bufb = sb + (uint32_t)(kt & 1) * AB_SIZE;
        if (kt + 1 < ntiles) {
            stageKV(kt + 1, sb + (uint32_t)((kt + 1) & 1) * AB_SIZE);
            CP_WAIT(1);
        } else {
            CP_WAIT(0);
        }
        __syncthreads();

        uint32_t skh = bufb, skl = bufb + 8192;
        uint32_t svh = bufb + 16384, svl = bufb + 24576;

        // ---- S = Q K^T (3 passes) ----
        float s[8][4];
#pragma unroll
        for (int i = 0; i < 8; i++)
#pragma unroll
            for (int j = 0; j < 4; j++) s[i][j] = 0.f;

#pragma unroll
        for (int ks = 0; ks < 4; ks++) {
#pragma unroll
            for (int nn = 0; nn < 4; nn++) {
                uint32_t off = SW128((uint32_t)((nn*16 + b_row)*128 + ks*32 + b_cb));
                uint32_t k0, k1, k2, k3, c0, c1, c2, c3;
                LDSM_X4(k0, k1, k2, k3, skh + off);
                LDSM_X4(c0, c1, c2, c3, skl + off);
                MMA_BF16(s[nn*2],   qh[ks][0], qh[ks][1], qh[ks][2], qh[ks][3], k0, k1);
                MMA_BF16(s[nn*2+1], qh[ks][0], qh[ks][1], qh[ks][2], qh[ks][3], k2, k3);
                MMA_BF16(s[nn*2],   qh[ks][0], qh[ks][1], qh[ks][2], qh[ks][3], c0, c1);
                MMA_BF16(s[nn*2+1], qh[ks][0], qh[ks][1], qh[ks][2], qh[ks][3], c2, c3);
                MMA_BF16(s[nn*2],   ql[ks][0], ql[ks][1], ql[ks][2], ql[ks][3], k0, k1);
                MMA_BF16(s[nn*2+1], ql[ks][0], ql[ks][1], ql[ks][2], ql[ks][3], k2, k3);
            }
        }

        // ---- scale + causal mask ----
        if (kt == qt) {
#pragma unroll
            for (int ni = 0; ni < 8; ni++)
#pragma unroll
                for (int j = 0; j < 4; j++) {
                    int ct = ni*8 + 2*t4 + (j & 1);
                    int rt = wid*16 + g + ((j >> 1) << 3);
                    s[ni][j] = (ct <= rt) ? s[ni][j] * 0.125f : -INFINITY;
                }
        } else {
#pragma unroll
            for (int ni = 0; ni < 8; ni++)
#pragma unroll
                for (int j = 0; j < 4; j++) s[ni][j] *= 0.125f;
        }

        // ---- online softmax ----
        float mt0 = m0, mt1 = m1;
#pragma unroll
        for (int ni = 0; ni < 8; ni++) {
            mt0 = fmaxf(mt0, fmaxf(s[ni][0], s[ni][1]));
            mt1 = fmaxf(mt1, fmaxf(s[ni][2], s[ni][3]));
        }
        mt0 = fmaxf(mt0, __shfl_xor_sync(0xffffffffu, mt0, 1));
        mt0 = fmaxf(mt0, __shfl_xor_sync(0xffffffffu, mt0, 2));
        mt1 = fmaxf(mt1, __shfl_xor_sync(0xffffffffu, mt1, 1));
        mt1 = fmaxf(mt1, __shfl_xor_sync(0xffffffffu, mt1, 2));

        float alpha0 = __expf(m0 - mt0);
        float alpha1 = __expf(m1 - mt1);
        m0 = mt0; m1 = mt1;

        float ps0 = 0.f, ps1 = 0.f;
#pragma unroll
        for (int ni = 0; ni < 8; ni++) {
            s[ni][0] = __expf(s[ni][0] - m0);
            s[ni][1] = __expf(s[ni][1] - m0);
            s[ni][2] = __expf(s[ni][2] - m1);
            s[ni][3] = __expf(s[ni][3] - m1);
            ps0 += s[ni][0] + s[ni][1];
            ps1 += s[ni][2] + s[ni][3];
        }
        ps0 += __shfl_xor_sync(0xffffffffu, ps0, 1);
        ps0 += __shfl_xor_sync(0xffffffffu, ps0, 2);
        ps1 += __shfl_xor_sync(0xffffffffu, ps1, 1);
        ps1 += __shfl_xor_sync(0xffffffffu, ps1, 2);
        l0 = l0 * alpha0 + ps0;
        l1 = l1 * alpha1 + ps1;

#pragma unroll
        for (int dt = 0; dt < 8; dt++) {
            o[dt][0] *= alpha0; o[dt][1] *= alpha0;
            o[dt][2] *= alpha1; o[dt][3] *= alpha1;
        }

        // ---- P fragments, split hi/lo in regs ----
        uint32_t ph[4][4], pl[4][4];
#pragma unroll
        for (int kc = 0; kc < 4; kc++) {
            float x0 = s[2*kc][0],   x1 = s[2*kc][1],   x2 = s[2*kc][2],   x3 = s[2*kc][3];
            float y0 = s[2*kc+1][0], y1 = s[2*kc+1][1], y2 = s[2*kc+1][2], y3 = s[2*kc+1][3];
            ph[kc][0] = pack2_hi(x0, x1);
            ph[kc][1] = pack2_hi(x2, x3);
            ph[kc][2] = pack2_hi(y0, y1);
            ph[kc][3] = pack2_hi(y2, y3);
            pl[kc][0] = pack2_rn(x0 - hi_trunc(x0), x1 - hi_trunc(x1));
            pl[kc][1] = pack2_rn(x2 - hi_trunc(x2), x3 - hi_trunc(x3));
            pl[kc][2] = pack2_rn(y0 - hi_trunc(y0), y1 - hi_trunc(y1));
            pl[kc][3] = pack2_rn(y2 - hi_trunc(y2), y3 - hi_trunc(y3));
        }

        // ---- O += P V (3 passes, V via ldmatrix.trans) ----
#pragma unroll
        for (int kc = 0; kc < 4; kc++) {
#pragma unroll
            for (int dn = 0; dn < 4; dn++) {
                uint32_t off = SW128((uint32_t)((kc*16 + v_row)*128 + dn*32 + v_cb));
                uint32_t vh0, vh1, vh2, vh3, vl0, vl1, vl2, vl3;
                LDSM_X4_T(vh0, vh1, vh2, vh3, svh + off);
                LDSM_X4_T(vl0, vl1, vl2, vl3, svl + off);
                MMA_BF16(o[dn*2],   ph[kc][0], ph[kc][1], ph[kc][2], ph[kc][3], vh0, vh1);
                MMA_BF16(o[dn*2+1], ph[kc][0], ph[kc][1], ph[kc][2], ph[kc][3], vh2, vh3);
                MMA_BF16(o[dn*2],   ph[kc][0], ph[kc][1], ph[kc][2], ph[kc][3], vl0, vl1);
                MMA_BF16(o[dn*2+1], ph[kc][0], ph[kc][1], ph[kc][2], ph[kc][3], vl2, vl3);
                MMA_BF16(o[dn*2],   pl[kc][0], pl[kc][1], pl[kc][2], pl[kc][3], vh0, vh1);
                MMA_BF16(o[dn*2+1], pl[kc][0], pl[kc][1], pl[kc][2], pl[kc][3], vh2, vh3);
            }
        }
        __syncthreads();   // all warps done with this buffer before re-stage
    }

    // ---- epilogue: normalize, write split bf16 into g_yh/g_yl ----
    float inv0 = 1.f / l0, inv1 = 1.f / l1;
    int b = bh >> 4, h = bh & 15;
    int row0 = q0 + wid*16 + g;
    int row1 = row0 + 8;
    size_t off0 = ((size_t)b*TT + row0)*CC + h*HD;
    size_t off1 = ((size_t)b*TT + row1)*CC + h*HD;
#pragma unroll
    for (int dt = 0; dt < 8; dt++) {
        int d = dt*8 + 2*t4;
        float w0x = o[dt][0]*inv0, w0y = o[dt][1]*inv0;
        float w1x = o[dt][2]*inv1, w1y = o[dt][3]*inv1;
        ((uint32_t*)g_yh)[(off0 + d) >> 1] = pack2_hi(w0x, w0y);
        ((uint32_t*)g_yl)[(off0 + d) >> 1] =
            pack2_rn(w0x - hi_trunc(w0x), w0y - hi_trunc(w0y));
        ((uint32_t*)g_yh)[(off1 + d) >> 1] = pack2_hi(w1x, w1y);
        ((uint32_t*)g_yl)[(off1 + d) >> 1] =
            pack2_rn(w1x - hi_trunc(w1x), w1y - hi_trunc(w1y));
    }
}

// ---------------------------------------------------------------------------
extern "C" void kernel_launch(void* const* d_in, const int* in_sizes, int n_in,
                              void* d_out, int out_size)
{
    const float* x      = (const float*)d_in[0];
    const float* W_attn = (const float*)d_in[1];
    const float* b_attn = (const float*)d_in[2];
    const float* W_proj = (const float*)d_in[3];
    const float* b_proj = (const float*)d_in[4];
    float* out = (float*)d_out;

    cudaFuncSetAttribute(gemm_tc<1>, cudaFuncAttributeMaxDynamicSharedMemorySize, SM_TOTAL);
    cudaFuncSetAttribute(gemm_tc<2>, cudaFuncAttributeMaxDynamicSharedMemorySize, SM_TOTAL);
    cudaFuncSetAttribute(attn_tc,    cudaFuncAttributeMaxDynamicSharedMemorySize, ASM_TOTAL);

    // 0) one-time splits
    {
        __nv_bfloat16 *xh, *xl, *wah, *wal, *wph, *wpl;
        cudaGetSymbolAddress((void**)&xh,  g_xh);
        cudaGetSymbolAddress((void**)&xl,  g_xl);
        cudaGetSymbolAddress((void**)&wah, g_wah);
        cudaGetSymbolAddress((void**)&wal, g_wal);
        cudaGetSymbolAddress((void**)&wph, g_wph);
        cudaGetSymbolAddress((void**)&wpl, g_wpl);
        int n4x = M_TOT*CC/4, n4a = N_QKV*CC/4, n4p = CC*CC/4;
        convert_split<<<(n4x+255)/256, 256>>>((const float4*)x,
            (uint32_t*)xh, (uint32_t*)xl, n4x);
        convert_split<<<(n4a+255)/256, 256>>>((const float4*)W_attn,
            (uint32_t*)wah, (uint32_t*)wal, n4a);
        convert_split<<<(n4p+255)/256, 256>>>((const float4*)W_proj,
            (uint32_t*)wph, (uint32_t*)wpl, n4p);
    }

    // 1) QKV projection
    gemm_tc<1><<<dim3(N_QKV/128, M_TOT/128), 256, SM_TOTAL>>>(b_attn, nullptr, CC, N_QKV);
    // 2) causal flash attention (64-row Q tiles, cp.async double-buffered)
    attn_tc<<<dim3(TT/64, BB*HH), 128, ASM_TOTAL>>>();
    // 3) output projection
    gemm_tc<2><<<dim3(CC/128, M_TOT/128), 256, SM_TOTAL>>>(b_proj, out, CC, CC);
}

// round 15
// speedup vs baseline: 1.8227x; 1.1180x over previous
#include <cuda_runtime.h>
#include <cuda_bf16.h>
#include <math.h>
#include <stdint.h>

// Problem constants
#define BB 2
#define TT 2048
#define CC 1024
#define HH 16
#define HD 64
#define M_TOT (BB*TT)        // 4096
#define N_QKV (3*CC)         // 3072

// Scratch (device globals: allocation-free)
__device__ __nv_bfloat16 g_xh[M_TOT*CC],  g_xl[M_TOT*CC];
__device__ __nv_bfloat16 g_wah[N_QKV*CC], g_wal[N_QKV*CC];
__device__ __nv_bfloat16 g_wph[CC*CC],    g_wpl[CC*CC];
__device__ __nv_bfloat16 g_qh[BB*HH*TT*HD], g_ql[BB*HH*TT*HD];
__device__ __nv_bfloat16 g_kh[BB*HH*TT*HD], g_kl[BB*HH*TT*HD];
__device__ __nv_bfloat16 g_vh[BB*HH*TT*HD], g_vl[BB*HH*TT*HD];
__device__ __nv_bfloat16 g_yh[BB*TT*CC], g_yl[BB*TT*CC];

#define SW128(off)    ((off) ^ (((off) >> 3) & 0x70))

__device__ __forceinline__ uint32_t smem_u32(const void* p) {
    uint32_t a;
    asm("{ .reg .u64 t; cvta.to.shared.u64 t, %1; cvt.u32.u64 %0, t; }" : "=r"(a) : "l"(p));
    return a;
}

#define LDSM_X4(r0, r1, r2, r3, addr) \
    asm volatile("ldmatrix.sync.aligned.m8n8.x4.shared.b16 {%0,%1,%2,%3}, [%4];" \
                 : "=r"(r0), "=r"(r1), "=r"(r2), "=r"(r3) : "r"(addr))

#define LDSM_X4_T(r0, r1, r2, r3, addr) \
    asm volatile("ldmatrix.sync.aligned.m8n8.x4.trans.shared.b16 {%0,%1,%2,%3}, [%4];" \
                 : "=r"(r0), "=r"(r1), "=r"(r2), "=r"(r3) : "r"(addr))

#define MMA_BF16(d, a0, a1, a2, a3, b0, b1) \
    asm volatile("mma.sync.aligned.m16n8k16.row.col.f32.bf16.bf16.f32 " \
                 "{%0,%1,%2,%3}, {%4,%5,%6,%7}, {%8,%9}, {%0,%1,%2,%3};" \
                 : "+f"((d)[0]), "+f"((d)[1]), "+f"((d)[2]), "+f"((d)[3]) \
                 : "r"(a0), "r"(a1), "r"(a2), "r"(a3), "r"(b0), "r"(b1))

__device__ __forceinline__ void cp16(uint32_t dst, const void* src) {
    asm volatile("cp.async.cg.shared.global [%0], [%1], 16;" :: "r"(dst), "l"(src));
}
#define CP_COMMIT()   asm volatile("cp.async.commit_group;" ::: "memory")
#define CP_WAIT(n)    asm volatile("cp.async.wait_group %0;" :: "n"(n) : "memory")

__device__ __forceinline__ float hi_trunc(float x) {
    return __uint_as_float(__float_as_uint(x) & 0xFFFF0000u);
}
__device__ __forceinline__ uint32_t pack2_hi(float x, float y) {
    return (__float_as_uint(x) >> 16) | (__float_as_uint(y) & 0xFFFF0000u);
}
__device__ __forceinline__ uint32_t pack2_rn(float x, float y) {
    uint32_t r;
    asm("cvt.rn.bf16x2.f32 %0, %1, %2;" : "=r"(r) : "f"(y), "f"(x));
    return r;
}

// ===========================================================================
// One-time fp32 -> bf16 hi/lo split
// ===========================================================================
__global__ __launch_bounds__(256) void convert_split(
    const float4* __restrict__ src, uint32_t* __restrict__ hi,
    uint32_t* __restrict__ lo, int n4)
{
    int i = blockIdx.x * blockDim.x + threadIdx.x;
    if (i >= n4) return;
    float4 v = src[i];
    uint2 h, l;
    h.x = pack2_hi(v.x, v.y);
    h.y = pack2_hi(v.z, v.w);
    l.x = pack2_rn(v.x - hi_trunc(v.x), v.y - hi_trunc(v.y));
    l.y = pack2_rn(v.z - hi_trunc(v.z), v.w - hi_trunc(v.w));
    reinterpret_cast<uint2*>(hi)[i] = h;
    reinterpret_cast<uint2*>(lo)[i] = l;
}

// ===========================================================================
// Pipelined tensor-core GEMM v2: 128x64 tile, 4 warps (128 thr), 2 blocks/SM.
// Per buffer (48 KB): Ahi@0 (16K), Alo@16K, Bhi@32K (8K), Blo@40K.
// Fragment caching: per ks load ahi/alo/bhi/blo once -> 48 MMAs.
// MODE 1: QKV epilogue scatter (bf16 hi/lo). MODE 2: proj, fp32 store.
// ===========================================================================
#define GBUF      49152
#define GSM_TOTAL (2*GBUF)   // 96 KB -> 2 blocks/SM

template<int MODE>
__global__ __launch_bounds__(128) void gemm_tc(
    const float* __restrict__ bias, float* __restrict__ C, int K, int N)
{
    extern __shared__ char smem[];
    uint32_t sb  = smem_u32(smem);
    int tid = threadIdx.x;
    int wid = tid >> 5;
    int lid = tid & 31;

    const __nv_bfloat16 *Ah, *Al, *Bh, *Bl;
    if (MODE == 1) { Ah = g_xh; Al = g_xl; Bh = g_wah; Bl = g_wal; }
    else           { Ah = g_yh; Al = g_yl; Bh = g_wph; Bl = g_wpl; }

    int m0 = blockIdx.y * 128;
    int n0 = blockIdx.x * 64;

    int mw = (wid >> 1) * 64;    // warp M offset (0/64)
    int nw = (wid & 1)  * 32;    // warp N offset (0/32)

    int a_row = lid & 15;
    int a_cb  = (lid >> 4) * 16;
    int b_row = (lid & 7) + ((lid >> 4) << 3);
    int b_cb  = ((lid >> 3) & 1) * 16;

    const int nchunk = K / 64;

    auto stage = [&](int kc, int buf) {
        uint32_t base = sb + buf * GBUF;
        const __nv_bfloat16* Asrc_h = Ah + (size_t)m0 * K + kc * 64;
        const __nv_bfloat16* Asrc_l = Al + (size_t)m0 * K + kc * 64;
        const __nv_bfloat16* Bsrc_h = Bh + (size_t)n0 * K + kc * 64;
        const __nv_bfloat16* Bsrc_l = Bl + (size_t)n0 * K + kc * 64;
        // A: 1024 chunks each for hi/lo (128 rows x 8)
#pragma unroll
        for (int i = 0; i < 8; i++) {
            int idx = tid + i * 128;
            int row = idx >> 3, ch = idx & 7;
            uint32_t sw = SW128((uint32_t)(row*128 + ch*16));
            cp16(base + sw,         Asrc_h + (size_t)row * K + ch * 8);
            cp16(base + 16384 + sw, Asrc_l + (size_t)row * K + ch * 8);
        }
        // B: 512 chunks each for hi/lo (64 rows x 8)
#pragma unroll
        for (int i = 0; i < 4; i++) {
            int idx = tid + i * 128;
            int row = idx >> 3, ch = idx & 7;
            uint32_t sw = SW128((uint32_t)(row*128 + ch*16));
            cp16(base + 32768 + sw, Bsrc_h + (size_t)row * K + ch * 8);
            cp16(base + 40960 + sw, Bsrc_l + (size_t)row * K + ch * 8);
        }
        CP_COMMIT();
    };

    float acc[16][4];
#pragma unroll
    for (int i = 0; i < 16; i++)
#pragma unroll
        for (int j = 0; j < 4; j++) acc[i][j] = 0.f;

    stage(0, 0);

    for (int kc = 0; kc < nchunk; kc++) {
        int cur = kc & 1;
        if (kc + 1 < nchunk) { stage(kc + 1, cur ^ 1); CP_WAIT(1); }
        else                 { CP_WAIT(0); }
        __syncthreads();

        uint32_t bufb = sb + cur * GBUF;
#pragma unroll
        for (int ks = 0; ks < 4; ks++) {
            // cache all fragments for this ks once
            uint32_t ahi[4][4], alo[4][4];
#pragma unroll
            for (int mi = 0; mi < 4; mi++) {
                uint32_t off = SW128((uint32_t)((mw + mi*16 + a_row) * 128 + ks*32 + a_cb));
                LDSM_X4(ahi[mi][0], ahi[mi][1], ahi[mi][2], ahi[mi][3], bufb + off);
                LDSM_X4(alo[mi][0], alo[mi][1], alo[mi][2], alo[mi][3], bufb + 16384 + off);
            }
            uint32_t bhi[2][4], blo[2][4];
#pragma unroll
            for (int nn = 0; nn < 2; nn++) {
                uint32_t off = SW128((uint32_t)((nw + nn*16 + b_row) * 128 + ks*32 + b_cb));
                LDSM_X4(bhi[nn][0], bhi[nn][1], bhi[nn][2], bhi[nn][3], bufb + 32768 + off);
                LDSM_X4(blo[nn][0], blo[nn][1], blo[nn][2], blo[nn][3], bufb + 40960 + off);
            }
            // 48 MMAs: hi*hi, hi*lo, lo*hi
#pragma unroll
            for (int mi = 0; mi < 4; mi++)
#pragma unroll
                for (int ni = 0; ni < 4; ni++) {
                    int nn = ni >> 1, half = (ni & 1) * 2;
                    MMA_BF16(acc[mi*4+ni], ahi[mi][0], ahi[mi][1], ahi[mi][2], ahi[mi][3],
                             bhi[nn][half], bhi[nn][half+1]);
                    MMA_BF16(acc[mi*4+ni], ahi[mi][0], ahi[mi][1], ahi[mi][2], ahi[mi][3],
                             blo[nn][half], blo[nn][half+1]);
                    MMA_BF16(acc[mi*4+ni], alo[mi][0], alo[mi][1], alo[mi][2], alo[mi][3],
                             bhi[nn][half], bhi[nn][half+1]);
                }
        }
        __syncthreads();
    }

    int g  = lid >> 2;
    int t4 = lid & 3;
#pragma unroll
    for (int mi = 0; mi < 4; mi++) {
        int mrow0 = m0 + mw + mi*16 + g;
        int mrow1 = mrow0 + 8;
#pragma unroll
        for (int ni = 0; ni < 4; ni++) {
            int n = n0 + nw + ni*8 + 2*t4;
            float bv0 = bias[n], bv1 = bias[n+1];
            const float* a4 = acc[mi*4+ni];
            float2 v0; v0.x = a4[0] + bv0; v0.y = a4[1] + bv1;
            float2 v1; v1.x = a4[2] + bv0; v1.y = a4[3] + bv1;

            if (MODE == 1) {
                int which = n >> 10;
                int h = (n >> 6) & 15;
                int d = n & 63;
                __nv_bfloat16* ph_ = (which == 0 ? g_qh : which == 1 ? g_kh : g_vh);
                __nv_bfloat16* pl_ = (which == 0 ? g_ql : which == 1 ? g_kl : g_vl);
                {
                    int bb = mrow0 >> 11, t = mrow0 & 2047;
                    size_t i0 = ((((size_t)bb*HH + h)*TT) + t)*HD + d;
                    ((uint32_t*)ph_)[i0 >> 1] = pack2_hi(v0.x, v0.y);
                    ((uint32_t*)pl_)[i0 >> 1] =
                        pack2_rn(v0.x - hi_trunc(v0.x), v0.y - hi_trunc(v0.y));
                }
                {
                    int bb = mrow1 >> 11, t = mrow1 & 2047;
                    size_t i1 = ((((size_t)bb*HH + h)*TT) + t)*HD + d;
                    ((uint32_t*)ph_)[i1 >> 1] = pack2_hi(v1.x, v1.y);
                    ((uint32_t*)pl_)[i1 >> 1] =
                        pack2_rn(v1.x - hi_trunc(v1.x), v1.y - hi_trunc(v1.y));
                }
            } else {
                *reinterpret_cast<float2*>(C + (size_t)mrow0 * N + n) = v0;
                *reinterpret_cast<float2*>(C + (size_t)mrow1 * N + n) = v1;
            }
        }
    }
}

// ===========================================================================
// Tensor-core flash attention (byte-identical to R13)
// ===========================================================================
#define AB_SIZE   32768
#define ASM_TOTAL (2*AB_SIZE)

__global__ __launch_bounds__(128) void attn_tc()
{
    extern __shared__ char asmem[];
    uint32_t sb = smem_u32(asmem);

    int tid = threadIdx.x;
    int wid = tid >> 5;
    int lid = tid & 31;
    int qt  = (int)gridDim.x - 1 - (int)blockIdx.x;
    int bh  = blockIdx.y;
    int q0  = qt * 64;
    size_t hoff = (size_t)bh * (TT * HD);

    int g  = lid >> 2;
    int t4 = lid & 3;

    {
        const uint4* srch = reinterpret_cast<const uint4*>(g_qh + hoff + (size_t)q0*HD);
        const uint4* srcl = reinterpret_cast<const uint4*>(g_ql + hoff + (size_t)q0*HD);
#pragma unroll
        for (int i = 0; i < 4; i++) {
            int idx = tid + i*128;
            int row = idx >> 3, ch = idx & 7;
            uint32_t sw = SW128((uint32_t)(row*128 + ch*16));
            *reinterpret_cast<uint4*>(asmem + sw)        = srch[row*8 + ch];
            *reinterpret_cast<uint4*>(asmem + 8192 + sw) = srcl[row*8 + ch];
        }
    }
    __syncthreads();

    uint32_t qh[4][4], ql[4][4];
    int a_row = lid & 15, a_cb = (lid >> 4) * 16;
#pragma unroll
    for (int ks = 0; ks < 4; ks++) {
        uint32_t off = SW128((uint32_t)((wid*16 + a_row)*128 + ks*32 + a_cb));
        LDSM_X4(qh[ks][0], qh[ks][1], qh[ks][2], qh[ks][3], sb + off);
        LDSM_X4(ql[ks][0], ql[ks][1], ql[ks][2], ql[ks][3], sb + 8192 + off);
    }
    __syncthreads();

    float o[8][4];
#pragma unroll
    for (int i = 0; i < 8; i++)
#pragma unroll
        for (int j = 0; j < 4; j++) o[i][j] = 0.f;
    float m0 = -INFINITY, m1 = -INFINITY, l0 = 0.f, l1 = 0.f;

    int b_row = (lid & 7) + ((lid >> 4) << 3);
    int b_cb  = ((lid >> 3) & 1) * 16;
    int v_row = (lid & 7) + (((lid >> 3) & 1) << 3);
    int v_cb  = (lid >> 4) << 4;

    auto stageKV = [&](int kt, uint32_t base) {
        size_t toff = hoff + (size_t)kt*64*HD;
        const __nv_bfloat16* arrs[4] = { g_kh + toff, g_kl + toff,
                                         g_vh + toff, g_vl + toff };
#pragma unroll
        for (int i = 0; i < 16; i++) {
            int idx = tid + i*128;
            int t   = idx >> 9;
            int c   = idx & 511;
            int row = c >> 3, ch = c & 7;
            cp16(base + t*8192 + SW128((uint32_t)(row*128 + ch*16)),
                 arrs[t] + (size_t)row*HD + ch*8);
        }
        CP_COMMIT();
    };

    const int ntiles = qt + 1;
    stageKV(0, sb);

    for (int kt = 0; kt < ntiles; kt++) {
        uint32_t bufb = sb + (uint32_t)(kt & 1) * AB_SIZE;
        if (kt + 1 < ntiles) {
            stageKV(kt + 1, sb + (uint32_t)((kt + 1) & 1) * AB_SIZE);
            CP_WAIT(1);
        } else {
            CP_WAIT(0);
        }
        __syncthreads();

        uint32_t skh = bufb, skl = bufb + 8192;
        uint32_t svh = bufb + 16384, svl = bufb + 24576;

        float s[8][4];
#pragma unroll
        for (int i = 0; i < 8; i++)
#pragma unroll
            for (int j = 0; j < 4; j++) s[i][j] = 0.f;

#pragma unroll
        for (int ks = 0; ks < 4; ks++) {
#pragma unroll
            for (int nn = 0; nn < 4; nn++) {
                uint32_t off = SW128((uint32_t)((nn*16 + b_row)*128 + ks*32 + b_cb));
                uint32_t k0, k1, k2, k3, c0, c1, c2, c3;
                LDSM_X4(k0, k1, k2, k3, skh + off);
                LDSM_X4(c0, c1, c2, c3, skl + off);
                MMA_BF16(s[nn*2],   qh[ks][0], qh[ks][1], qh[ks][2], qh[ks][3], k0, k1);
                MMA_BF16(s[nn*2+1], qh[ks][0], qh[ks][1], qh[ks][2], qh[ks][3], k2, k3);
                MMA_BF16(s[nn*2],   qh[ks][0], qh[ks][1], qh[ks][2], qh[ks][3], c0, c1);
                MMA_BF16(s[nn*2+1], qh[ks][0], qh[ks][1], qh[ks][2], qh[ks][3], c2, c3);
                MMA_BF16(s[nn*2],   ql[ks][0], ql[ks][1], ql[ks][2], ql[ks][3], k0, k1);
                MMA_BF16(s[nn*2+1], ql[ks][0], ql[ks][1], ql[ks][2], ql[ks][3], k2, k3);
            }
        }

        if (kt == qt) {
#pragma unroll
            for (int ni = 0; ni < 8; ni++)
#pragma unroll
                for (int j = 0; j < 4; j++) {
                    int ct = ni*8 + 2*t4 + (j & 1);
                    int rt = wid*16 + g + ((j >> 1) << 3);
                    s[ni][j] = (ct <= rt) ? s[ni][j] * 0.125f : -INFINITY;
                }
        } else {
#pragma unroll
            for (int ni = 0; ni < 8; ni++)
#pragma unroll
                for (int j = 0; j < 4; j++) s[ni][j] *= 0.125f;
        }

        float mt0 = m0, mt1 = m1;
#pragma unroll
        for (int ni = 0; ni < 8; ni++) {
            mt0 = fmaxf(mt0, fmaxf(s[ni][0], s[ni][1]));
            mt1 = fmaxf(mt1, fmaxf(s[ni][2], s[ni][3]));
        }
        mt0 = fmaxf(mt0, __shfl_xor_sync(0xffffffffu, mt0, 1));
        mt0 = fmaxf(mt0, __shfl_xor_sync(0xffffffffu, mt0, 2));
        mt1 = fmaxf(mt1, __shfl_xor_sync(0xffffffffu, mt1, 1));
        mt1 = fmaxf(mt1, __shfl_xor_sync(0xffffffffu, mt1, 2));

        float alpha0 = __expf(m0 - mt0);
        float alpha1 = __expf(m1 - mt1);
        m0 = mt0; m1 = mt1;

        float ps0 = 0.f, ps1 = 0.f;
#pragma unroll
        for (int ni = 0; ni < 8; ni++) {
            s[ni][0] = __expf(s[ni][0] - m0);
            s[ni][1] = __expf(s[ni][1] - m0);
            s[ni][2] = __expf(s[ni][2] - m1);
            s[ni][3] = __expf(s[ni][3] - m1);
            ps0 += s[ni][0] + s[ni][1];
            ps1 += s[ni][2] + s[ni][3];
        }
        ps0 += __shfl_xor_sync(0xffffffffu, ps0, 1);
        ps0 += __shfl_xor_sync(0xffffffffu, ps0, 2);
        ps1 += __shfl_xor_sync(0xffffffffu, ps1, 1);
        ps1 += __shfl_xor_sync(0xffffffffu, ps1, 2);
        l0 = l0 * alpha0 + ps0;
        l1 = l1 * alpha1 + ps1;

#pragma unroll
        for (int dt = 0; dt < 8; dt++) {
            o[dt][0] *= alpha0; o[dt][1] *= alpha0;
            o[dt][2] *= alpha1; o[dt][3] *= alpha1;
        }

        uint32_t ph[4][4], pl[4][4];
#pragma unroll
        for (int kc = 0; kc < 4; kc++) {
            float x0 = s[2*kc][0],   x1 = s[2*kc][1],   x2 = s[2*kc][2],   x3 = s[2*kc][3];
            float y0 = s[2*kc+1][0], y1 = s[2*kc+1][1], y2 = s[2*kc+1][2], y3 = s[2*kc+1][3];
            ph[kc][0] = pack2_hi(x0, x1);
            ph[kc][1] = pack2_hi(x2, x3);
            ph[kc][2] = pack2_hi(y0, y1);
            ph[kc][3] = pack2_hi(y2, y3);
            pl[kc][0] = pack2_rn(x0 - hi_trunc(x0), x1 - hi_trunc(x1));
            pl[kc][1] = pack2_rn(x2 - hi_trunc(x2), x3 - hi_trunc(x3));
            pl[kc][2] = pack2_rn(y0 - hi_trunc(y0), y1 - hi_trunc(y1));
            pl[kc][3] = pack2_rn(y2 - hi_trunc(y2), y3 - hi_trunc(y3));
        }

#pragma unroll
        for (int kc = 0; kc < 4; kc++) {
#pragma unroll
            for (int dn = 0; dn < 4; dn++) {
                uint32_t off = SW128((uint32_t)((kc*16 + v_row)*128 + dn*32 + v_cb));
                uint32_t vh0, vh1, vh2, vh3, vl0, vl1, vl2, vl3;
                LDSM_X4_T(vh0, vh1, vh2, vh3, svh + off);
                LDSM_X4_T(vl0, vl1, vl2, vl3, svl + off);
                MMA_BF16(o[dn*2],   ph[kc][0], ph[kc][1], ph[kc][2], ph[kc][3], vh0, vh1);
                MMA_BF16(o[dn*2+1], ph[kc][0], ph[kc][1], ph[kc][2], ph[kc][3], vh2, vh3);
                MMA_BF16(o[dn*2],   ph[kc][0], ph[kc][1], ph[kc][2], ph[kc][3], vl0, vl1);
                MMA_BF16(o[dn*2+1], ph[kc][0], ph[kc][1], ph[kc][2], ph[kc][3], vl2, vl3);
                MMA_BF16(o[dn*2],   pl[kc][0], pl[kc][1], pl[kc][2], pl[kc][3], vh0, vh1);
                MMA_BF16(o[dn*2+1], pl[kc][0], pl[kc][1], pl[kc][2], pl[kc][3], vh2, vh3);
            }
        }
        __syncthreads();
    }

    float inv0 = 1.f / l0, inv1 = 1.f / l1;
    int b = bh >> 4, h = bh & 15;
    int row0 = q0 + wid*16 + g;
    int row1 = row0 + 8;
    size_t off0 = ((size_t)b*TT + row0)*CC + h*HD;
    size_t off1 = ((size_t)b*TT + row1)*CC + h*HD;
#pragma unroll
    for (int dt = 0; dt < 8; dt++) {
        int d = dt*8 + 2*t4;
        float w0x = o[dt][0]*inv0, w0y = o[dt][1]*inv0;
        float w1x = o[dt][2]*inv1, w1y = o[dt][3]*inv1;
        ((uint32_t*)g_yh)[(off0 + d) >> 1] = pack2_hi(w0x, w0y);
        ((uint32_t*)g_yl)[(off0 + d) >> 1] =
            pack2_rn(w0x - hi_trunc(w0x), w0y - hi_trunc(w0y));
        ((uint32_t*)g_yh)[(off1 + d) >> 1] = pack2_hi(w1x, w1y);
        ((uint32_t*)g_yl)[(off1 + d) >> 1] =
            pack2_rn(w1x - hi_trunc(w1x), w1y - hi_trunc(w1y));
    }
}

// ---------------------------------------------------------------------------
extern "C" void kernel_launch(void* const* d_in, const int* in_sizes, int n_in,
                              void* d_out, int out_size)
{
    const float* x      = (const float*)d_in[0];
    const float* W_attn = (const float*)d_in[1];
    const float* b_attn = (const float*)d_in[2];
    const float* W_proj = (const float*)d_in[3];
    const float* b_proj = (const float*)d_in[4];
    float* out = (float*)d_out;

    cudaFuncSetAttribute(gemm_tc<1>, cudaFuncAttributeMaxDynamicSharedMemorySize, GSM_TOTAL);
    cudaFuncSetAttribute(gemm_tc<2>, cudaFuncAttributeMaxDynamicSharedMemorySize, GSM_TOTAL);
    cudaFuncSetAttribute(attn_tc,    cudaFuncAttributeMaxDynamicSharedMemorySize, ASM_TOTAL);

    // 0) one-time splits
    {
        __nv_bfloat16 *xh, *xl, *wah, *wal, *wph, *wpl;
        cudaGetSymbolAddress((void**)&xh,  g_xh);
        cudaGetSymbolAddress((void**)&xl,  g_xl);
        cudaGetSymbolAddress((void**)&wah, g_wah);
        cudaGetSymbolAddress((void**)&wal, g_wal);
        cudaGetSymbolAddress((void**)&wph, g_wph);
        cudaGetSymbolAddress((void**)&wpl, g_wpl);
        int n4x = M_TOT*CC/4, n4a = N_QKV*CC/4, n4p = CC*CC/4;
        convert_split<<<(n4x+255)/256, 256>>>((const float4*)x,
            (uint32_t*)xh, (uint32_t*)xl, n4x);
        convert_split<<<(n4a+255)/256, 256>>>((const float4*)W_attn,
            (uint32_t*)wah, (uint32_t*)wal, n4a);
        convert_split<<<(n4p+255)/256, 256>>>((const float4*)W_proj,
            (uint32_t*)wph, (uint32_t*)wpl, n4p);
    }

    // 1) QKV projection (128x64 tiles, 2 blocks/SM)
    gemm_tc<1><<<dim3(N_QKV/64, M_TOT/128), 128, GSM_TOTAL>>>(b_attn, nullptr, CC, N_QKV);
    // 2) causal flash attention
    attn_tc<<<dim3(TT/64, BB*HH), 128, ASM_TOTAL>>>();
    // 3) output projection
    gemm_tc<2><<<dim3(CC/64, M_TOT/128), 128, GSM_TOTAL>>>(b_proj, out, CC, CC);
}